// round 1
// baseline (speedup 1.0000x reference)
#include <cuda_runtime.h>
#include <cstdint>
#include <cstddef>

// Problem constants
#define BB   4
#define SS   2048
#define HH   16
#define DKK  64
#define DD   1024
#define RR   256
#define MROWS (BB*SS)   // 8192

static const size_t OUT_ELEMS  = (size_t)BB * SS * DD;        // 8388608
static const size_t ATTN_ELEMS = (size_t)BB * HH * SS * SS;   // 268435456

// Scratch (allocation-free rule: __device__ globals)
__device__ float g_tmp [MROWS * RR];          //  8 MB
__device__ float g_qh  [MROWS * DD];          // 32 MB
__device__ float g_kh  [MROWS * DD];          // 32 MB
__device__ float g_vh  [MROWS * DD];          // 32 MB
__device__ float g_ctx [MROWS * DD];          // 32 MB
__device__ float g_pre [MROWS * DD];          // 32 MB
__device__ float g_attn[(size_t)BB * HH * SS * SS]; // 1 GiB fallback if attn not in d_out

// ---------------------------------------------------------------------------
// Generic fp32 GEMM: C[M,N] = A[M,K] @ B[K,N] (+ add[M,N] if non-null)
// 64x64 block tile, K-tile 16, 256 threads, 4x4 microtile.
// ---------------------------------------------------------------------------
__global__ __launch_bounds__(256)
void sgemm64(const float* __restrict__ A, const float* __restrict__ Bm,
             const float* __restrict__ add, float* __restrict__ C,
             int M, int N, int K)
{
    const int BM = 64, BN = 64, BK = 16;
    __shared__ float As[BK][BM + 1];
    __shared__ float Bs[BK][BN + 1];

    const int tx = threadIdx.x & 15;
    const int ty = threadIdx.x >> 4;
    const int row0 = blockIdx.y * BM;
    const int col0 = blockIdx.x * BN;

    float acc[4][4] = {};

    for (int k0 = 0; k0 < K; k0 += BK) {
        #pragma unroll
        for (int i = 0; i < 4; i++) {
            int idx = threadIdx.x + 256 * i;      // 0..1023
            int ra = idx >> 4, ca = idx & 15;     // A[row0+ra][k0+ca]
            As[ca][ra] = A[(size_t)(row0 + ra) * K + k0 + ca];
            int rb = idx >> 6, cb = idx & 63;     // B[k0+rb][col0+cb]
            Bs[rb][cb] = Bm[(size_t)(k0 + rb) * N + col0 + cb];
        }
        __syncthreads();

        #pragma unroll
        for (int kk = 0; kk < BK; kk++) {
            float a[4], b[4];
            #pragma unroll
            for (int i = 0; i < 4; i++) a[i] = As[kk][ty * 4 + i];
            #pragma unroll
            for (int j = 0; j < 4; j++) b[j] = Bs[kk][tx * 4 + j];
            #pragma unroll
            for (int i = 0; i < 4; i++)
                #pragma unroll
                for (int j = 0; j < 4; j++)
                    acc[i][j] = fmaf(a[i], b[j], acc[i][j]);
        }
        __syncthreads();
    }

    #pragma unroll
    for (int i = 0; i < 4; i++) {
        #pragma unroll
        for (int j = 0; j < 4; j++) {
            size_t ci = (size_t)(row0 + ty * 4 + i) * N + col0 + tx * 4 + j;
            float v = acc[i][j];
            if (add) v += add[ci];
            C[ci] = v;
        }
    }
}

// ---------------------------------------------------------------------------
// scores[b,h,i,j] = sum_d (qh[b,i,h*64+d]/8) * kh[b,j,h*64+d]
// grid (S/64, S/64, B*H), 256 threads
// ---------------------------------------------------------------------------
__global__ __launch_bounds__(256)
void scores_kernel(const float* __restrict__ qh, const float* __restrict__ kh,
                   float* __restrict__ attn)
{
    __shared__ float Qs[64][DKK + 1];
    __shared__ float Ks[64][DKK + 1];

    const int bh = blockIdx.z;
    const int b = bh / HH, h = bh % HH;
    const int i0 = blockIdx.y * 64, j0 = blockIdx.x * 64;

    const float* qb = qh + (size_t)b * SS * DD + (size_t)h * DKK;
    const float* kb = kh + (size_t)b * SS * DD + (size_t)h * DKK;

    for (int t = threadIdx.x; t < 64 * 64; t += 256) {
        int r = t >> 6, c = t & 63;
        Qs[r][c] = qb[(size_t)(i0 + r) * DD + c] * 0.125f;
        Ks[r][c] = kb[(size_t)(j0 + r) * DD + c];
    }
    __syncthreads();

    const int tx = threadIdx.x & 15;
    const int ty = threadIdx.x >> 4;
    float acc[4][4] = {};

    #pragma unroll 8
    for (int d = 0; d < DKK; d++) {
        float a[4], bv[4];
        #pragma unroll
        for (int i = 0; i < 4; i++) a[i] = Qs[ty * 4 + i][d];
        #pragma unroll
        for (int j = 0; j < 4; j++) bv[j] = Ks[tx * 4 + j][d];
        #pragma unroll
        for (int i = 0; i < 4; i++)
            #pragma unroll
            for (int j = 0; j < 4; j++)
                acc[i][j] = fmaf(a[i], bv[j], acc[i][j]);
    }

    float* out = attn + ((size_t)bh * SS + i0) * SS + j0;
    #pragma unroll
    for (int i = 0; i < 4; i++)
        #pragma unroll
        for (int j = 0; j < 4; j++)
            out[(size_t)(ty * 4 + i) * SS + tx * 4 + j] = acc[i][j];
}

// ---------------------------------------------------------------------------
// In-place row softmax over 2048 elements. grid = B*H*S blocks, 256 threads.
// ---------------------------------------------------------------------------
__global__ __launch_bounds__(256)
void softmax_kernel(float* __restrict__ attn)
{
    __shared__ float red[8];
    float* p = attn + (size_t)blockIdx.x * SS;
    const int tid = threadIdx.x;

    float vals[8];
    float m = -1e30f;
    #pragma unroll
    for (int i = 0; i < 8; i++) {
        vals[i] = p[tid + 256 * i];
        m = fmaxf(m, vals[i]);
    }
    #pragma unroll
    for (int o = 16; o > 0; o >>= 1) m = fmaxf(m, __shfl_xor_sync(0xFFFFFFFFu, m, o));
    if ((tid & 31) == 0) red[tid >> 5] = m;
    __syncthreads();
    m = red[0];
    #pragma unroll
    for (int w = 1; w < 8; w++) m = fmaxf(m, red[w]);
    __syncthreads();

    float s = 0.f;
    #pragma unroll
    for (int i = 0; i < 8; i++) {
        vals[i] = __expf(vals[i] - m);
        s += vals[i];
    }
    #pragma unroll
    for (int o = 16; o > 0; o >>= 1) s += __shfl_xor_sync(0xFFFFFFFFu, s, o);
    if ((tid & 31) == 0) red[tid >> 5] = s;
    __syncthreads();
    s = red[0];
    #pragma unroll
    for (int w = 1; w < 8; w++) s += red[w];
    float inv = 1.0f / s;

    #pragma unroll
    for (int i = 0; i < 8; i++) p[tid + 256 * i] = vals[i] * inv;
}

// ---------------------------------------------------------------------------
// ctx[b, i, h*64+d] = sum_j attn[b,h,i,j] * vh[b, j, h*64+d]
// grid (S/64, B*H), 256 threads
// ---------------------------------------------------------------------------
__global__ __launch_bounds__(256)
void ctx_kernel(const float* __restrict__ attn, const float* __restrict__ vh,
                float* __restrict__ ctx)
{
    const int BK = 32;
    __shared__ float As[64][BK + 1];
    __shared__ float Vs[BK][64 + 1];

    const int bh = blockIdx.y;
    const int b = bh / HH, h = bh % HH;
    const int i0 = blockIdx.x * 64;

    const float* arow = attn + ((size_t)bh * SS + i0) * SS;
    const float* vb   = vh + (size_t)b * SS * DD + (size_t)h * DKK;

    const int tx = threadIdx.x & 15;
    const int ty = threadIdx.x >> 4;
    float acc[4][4] = {};

    for (int k0 = 0; k0 < SS; k0 += BK) {
        for (int t = threadIdx.x; t < 64 * BK; t += 256) {
            int r = t >> 5, c = t & 31;
            As[r][c] = arow[(size_t)r * SS + k0 + c];
        }
        for (int t = threadIdx.x; t < BK * 64; t += 256) {
            int r = t >> 6, c = t & 63;
            Vs[r][c] = vb[(size_t)(k0 + r) * DD + c];
        }
        __syncthreads();

        #pragma unroll
        for (int kk = 0; kk < BK; kk++) {
            float a[4], bv[4];
            #pragma unroll
            for (int i = 0; i < 4; i++) a[i] = As[ty * 4 + i][kk];
            #pragma unroll
            for (int j = 0; j < 4; j++) bv[j] = Vs[kk][tx * 4 + j];
            #pragma unroll
            for (int i = 0; i < 4; i++)
                #pragma unroll
                for (int j = 0; j < 4; j++)
                    acc[i][j] = fmaf(a[i], bv[j], acc[i][j]);
        }
        __syncthreads();
    }

    float* crow = ctx + ((size_t)b * SS + i0) * DD + (size_t)h * DKK;
    #pragma unroll
    for (int i = 0; i < 4; i++)
        #pragma unroll
        for (int j = 0; j < 4; j++)
            crow[(size_t)(ty * 4 + i) * DD + tx * 4 + j] = acc[i][j];
}

// ---------------------------------------------------------------------------
// LayerNorm over D=1024, eps=1e-6. grid = MROWS blocks, 256 threads.
// ---------------------------------------------------------------------------
__global__ __launch_bounds__(256)
void ln_kernel(const float* __restrict__ x, const float* __restrict__ gamma,
               const float* __restrict__ beta, float* __restrict__ out)
{
    __shared__ float reds[8], redq[8];
    const float* p = x + (size_t)blockIdx.x * DD;
    const int tid = threadIdx.x;

    float v[4];
    float s = 0.f, sq = 0.f;
    #pragma unroll
    for (int i = 0; i < 4; i++) {
        v[i] = p[tid + 256 * i];
        s += v[i];
        sq = fmaf(v[i], v[i], sq);
    }
    #pragma unroll
    for (int o = 16; o > 0; o >>= 1) {
        s  += __shfl_xor_sync(0xFFFFFFFFu, s,  o);
        sq += __shfl_xor_sync(0xFFFFFFFFu, sq, o);
    }
    if ((tid & 31) == 0) { reds[tid >> 5] = s; redq[tid >> 5] = sq; }
    __syncthreads();
    s = 0.f; sq = 0.f;
    #pragma unroll
    for (int w = 0; w < 8; w++) { s += reds[w]; sq += redq[w]; }

    const float mean = s * (1.0f / DD);
    const float var  = sq * (1.0f / DD) - mean * mean;
    const float inv  = rsqrtf(var + 1e-6f);

    float* o = out + (size_t)blockIdx.x * DD;
    #pragma unroll
    for (int i = 0; i < 4; i++) {
        int c = tid + 256 * i;
        o[c] = (v[i] - mean) * inv * gamma[c] + beta[c];
    }
}

// ---------------------------------------------------------------------------
extern "C" void kernel_launch(void* const* d_in, const int* in_sizes, int n_in,
                              void* d_out, int out_size)
{
    const float* q      = (const float*)d_in[0];
    const float* k      = (const float*)d_in[1];
    const float* v      = (const float*)d_in[2];
    const float* w_qs_u = (const float*)d_in[3];
    const float* w_qs_v = (const float*)d_in[4];
    const float* w_ks_u = (const float*)d_in[5];
    const float* w_ks_v = (const float*)d_in[6];
    const float* w_vs_u = (const float*)d_in[7];
    const float* w_vs_v = (const float*)d_in[8];
    const float* fc_u   = (const float*)d_in[9];
    const float* fc_v   = (const float*)d_in[10];
    const float* gamma  = (const float*)d_in[11];
    const float* beta   = (const float*)d_in[12];

    float* tmp;  cudaGetSymbolAddress((void**)&tmp,  g_tmp);
    float* qh;   cudaGetSymbolAddress((void**)&qh,   g_qh);
    float* kh;   cudaGetSymbolAddress((void**)&kh,   g_kh);
    float* vh;   cudaGetSymbolAddress((void**)&vh,   g_vh);
    float* ctx;  cudaGetSymbolAddress((void**)&ctx,  g_ctx);
    float* pre;  cudaGetSymbolAddress((void**)&pre,  g_pre);
    float* asc;  cudaGetSymbolAddress((void**)&asc,  g_attn);

    float* outp = nullptr;
    float* attn = nullptr;
    const size_t osz = (size_t)out_size;
    if (osz >= OUT_ELEMS + ATTN_ELEMS) {           // tuple: out then attn
        outp = (float*)d_out;
        attn = (float*)d_out + OUT_ELEMS;
    } else if (osz == ATTN_ELEMS) {                // attn only
        attn = (float*)d_out;
    } else {                                       // out only; attn to scratch
        outp = (float*)d_out;
        attn = asc;
    }

    const dim3 blk(256);

    // Low-rank projections: x @ U (8192x1024x256), then @ V (8192x256x1024)
    {
        dim3 g1(RR / 64, MROWS / 64);   // (4, 128)
        dim3 g2(DD / 64, MROWS / 64);   // (16, 128)
        sgemm64<<<g1, blk>>>(q, w_qs_u, nullptr, tmp, MROWS, RR, DD);
        sgemm64<<<g2, blk>>>(tmp, w_qs_v, nullptr, qh, MROWS, DD, RR);
        sgemm64<<<g1, blk>>>(k, w_ks_u, nullptr, tmp, MROWS, RR, DD);
        sgemm64<<<g2, blk>>>(tmp, w_ks_v, nullptr, kh, MROWS, DD, RR);
        sgemm64<<<g1, blk>>>(v, w_vs_u, nullptr, tmp, MROWS, RR, DD);
        sgemm64<<<g2, blk>>>(tmp, w_vs_v, nullptr, vh, MROWS, DD, RR);
    }

    // Attention
    {
        dim3 gs(SS / 64, SS / 64, BB * HH);        // (32, 32, 64)
        scores_kernel<<<gs, blk>>>(qh, kh, attn);
        softmax_kernel<<<BB * HH * SS, blk>>>(attn);
        dim3 gc(SS / 64, BB * HH);                 // (32, 64)
        ctx_kernel<<<gc, blk>>>(attn, vh, ctx);
    }

    // FC (low-rank) + residual + LayerNorm
    if (outp) {
        dim3 g1(RR / 64, MROWS / 64);
        dim3 g2(DD / 64, MROWS / 64);
        sgemm64<<<g1, blk>>>(ctx, fc_u, nullptr, tmp, MROWS, RR, DD);
        sgemm64<<<g2, blk>>>(tmp, fc_v, q /* residual */, pre, MROWS, DD, RR);
        ln_kernel<<<MROWS, blk>>>(pre, gamma, beta, outp);
    }
}

// round 5
// speedup vs baseline: 4.2645x; 4.2645x over previous
#include <cuda_runtime.h>
#include <cuda_fp16.h>
#include <cstdint>
#include <cstddef>

// Problem constants
#define BB   4
#define SS   2048
#define HH   16
#define DKK  64
#define DD   1024
#define RR   256
#define MROWS (BB*SS)   // 8192
#define ZBH  (BB*HH)    // 64

static const size_t OUT_ELEMS  = (size_t)BB * SS * DD;        // 8388608
static const size_t ATTN_ELEMS = (size_t)BB * HH * SS * SS;   // 268435456

// ---------------------------------------------------------------------------
// Scratch (__device__ globals; allocation-free rule)
// ---------------------------------------------------------------------------
__device__ __align__(128) __half g_q16 [MROWS * DD];
__device__ __align__(128) __half g_k16 [MROWS * DD];
__device__ __align__(128) __half g_v16 [MROWS * DD];
__device__ __align__(128) __half g_tmp16[MROWS * RR];
__device__ __align__(128) __half g_qh16[MROWS * DD];
__device__ __align__(128) __half g_kh16[MROWS * DD];
__device__ __align__(128) __half g_vh16[MROWS * DD];
__device__ __align__(128) __half g_vhT16[(size_t)ZBH * DKK * SS];   // [z][d][s]
__device__ __align__(128) __half g_ctx16[MROWS * DD];
__device__ __align__(128) __half g_attn16[(size_t)ZBH * SS * SS];   // exp(scores)
__device__ __align__(128) float  g_rowsum[(size_t)ZBH * SS];
__device__ __align__(128) float  g_pre [MROWS * DD];
// transposed fp16 weights [N][K]
__device__ __align__(128) __half g_wqsuT[RR * DD];
__device__ __align__(128) __half g_wqsvT[DD * RR];
__device__ __align__(128) __half g_wksuT[RR * DD];
__device__ __align__(128) __half g_wksvT[DD * RR];
__device__ __align__(128) __half g_wvsuT[RR * DD];
__device__ __align__(128) __half g_wvsvT[DD * RR];
__device__ __align__(128) __half g_fcuT [RR * DD];
__device__ __align__(128) __half g_fcvT [DD * RR];

// ---------------------------------------------------------------------------
// PTX helpers (arch-portable: cp.async / ldmatrix / mma.sync only)
// ---------------------------------------------------------------------------
__device__ __forceinline__ uint32_t smem_u32(const void* p) {
    uint32_t a;
    asm("{ .reg .u64 t; cvta.to.shared.u64 t, %1; cvt.u32.u64 %0, t; }" : "=r"(a) : "l"(p));
    return a;
}
__device__ __forceinline__ void cp16(uint32_t d, const void* s) {
    asm volatile("cp.async.cg.shared.global [%0], [%1], 16;" :: "r"(d), "l"(s) : "memory");
}
__device__ __forceinline__ void cp_commit() {
    asm volatile("cp.async.commit_group;" ::: "memory");
}
template<int N> __device__ __forceinline__ void cp_wait() {
    asm volatile("cp.async.wait_group %0;" :: "n"(N) : "memory");
}
__device__ __forceinline__ void ldsm4(uint32_t* r, uint32_t addr) {
    asm volatile("ldmatrix.sync.aligned.m8n8.x4.shared.b16 {%0,%1,%2,%3}, [%4];"
                 : "=r"(r[0]), "=r"(r[1]), "=r"(r[2]), "=r"(r[3]) : "r"(addr));
}
__device__ __forceinline__ void mma16816(float* c, const uint32_t* a, const uint32_t* b) {
    asm volatile("mma.sync.aligned.m16n8k16.row.col.f32.f16.f16.f32 "
                 "{%0,%1,%2,%3}, {%4,%5,%6,%7}, {%8,%9}, {%0,%1,%2,%3};"
                 : "+f"(c[0]), "+f"(c[1]), "+f"(c[2]), "+f"(c[3])
                 : "r"(a[0]), "r"(a[1]), "r"(a[2]), "r"(a[3]), "r"(b[0]), "r"(b[1]));
}
#define SWZ(o) ((o) ^ (((o) >> 3) & 0x70))

// ---------------------------------------------------------------------------
// HMMA fp16 GEMM: C[z, M, N] = sum_k A[z,m,k] * B[z,n,k]  (A,B K-major fp16)
// Block tile 128 x NT, K-tile 64, 256 threads (8 warps), double-buffered.
// EPI: 0 = fp16 store (* scale), 2 = exp + rowsum atomics + fp16 store,
//      3 = * 1/rowsum[row] + fp16 store, 4 = + resid, fp32 store.
// ---------------------------------------------------------------------------
struct GP {
    const __half* A; const __half* B; void* C;
    const float* resid; float* aux;
    long long sAb, sAh, sBb, sBh, sCb, sCh;
    int lda, ldb, ldc, K;
    float scale;
};

template<int NT, int EPI>
__global__ __launch_bounds__(256)
void hgemm_mma(GP p)
{
    constexpr int WARPS_M = (NT == 128) ? 2 : 4;
    constexpr int WARPS_N = 8 / WARPS_M;
    constexpr int WM = 128 / WARPS_M;        // 64 or 32
    constexpr int WN = NT / WARPS_N;         // 32
    constexpr int MF = WM / 16;              // 4 or 2
    constexpr int NF = WN / 8;               // 4
    constexpr int ABYTES = 128 * 128;        // 128 rows x 128B (64 halves)
    constexpr int BBYTES = NT * 128;
    constexpr int BUF = ABYTES + BBYTES;

    extern __shared__ char smem[];
    const uint32_t sb = smem_u32(smem);
    const int tid = threadIdx.x, lane = tid & 31, wid = tid >> 5;
    const int wm = (wid / WARPS_N) * WM;
    const int wn = (wid % WARPS_N) * WN;

    const int z  = blockIdx.z;
    const int m0 = blockIdx.y * 128;
    const int n0 = blockIdx.x * NT;

    const __half* Ab = p.A + (long long)(z >> 4) * p.sAb + (long long)(z & 15) * p.sAh;
    const __half* Bb = p.B + (long long)(z >> 4) * p.sBb + (long long)(z & 15) * p.sBh;

    float acc[MF][NF][4];
    #pragma unroll
    for (int i = 0; i < MF; i++)
        #pragma unroll
        for (int j = 0; j < NF; j++)
            #pragma unroll
            for (int e = 0; e < 4; e++) acc[i][j][e] = 0.f;

    auto loadtile = [&](int t, int buf) {
        const uint32_t base = sb + buf * BUF;
        const __half* Ag = Ab + (long long)m0 * p.lda + t * 64;
        #pragma unroll
        for (int i = 0; i < 4; i++) {
            int idx = tid + 256 * i;
            int r = idx >> 3, c = idx & 7;
            cp16(base + SWZ(r * 128 + c * 16), Ag + (long long)r * p.lda + c * 8);
        }
        const __half* Bg = Bb + (long long)n0 * p.ldb + t * 64;
        #pragma unroll
        for (int i = 0; i < NT / 32; i++) {
            int idx = tid + 256 * i;
            int r = idx >> 3, c = idx & 7;
            cp16(base + ABYTES + SWZ(r * 128 + c * 16), Bg + (long long)r * p.ldb + c * 8);
        }
        cp_commit();
    };

    auto compute = [&](int buf) {
        const uint32_t sa = sb + buf * BUF;
        const uint32_t sB = sa + ABYTES;
        #pragma unroll
        for (int kk = 0; kk < 4; kk++) {
            uint32_t afr[MF][4];
            #pragma unroll
            for (int mi = 0; mi < MF; mi++) {
                int row = wm + mi * 16 + (lane & 15);
                ldsm4(afr[mi], sa + SWZ(row * 128 + kk * 32 + (lane >> 4) * 16));
            }
            uint32_t bfr[NF][2];
            #pragma unroll
            for (int nj = 0; nj < NF; nj += 2) {
                int rowb = wn + nj * 8 + (lane & 7) + ((lane >> 4) & 1) * 8;
                uint32_t r4[4];
                ldsm4(r4, sB + SWZ(rowb * 128 + kk * 32 + ((lane >> 3) & 1) * 16));
                bfr[nj][0] = r4[0]; bfr[nj][1] = r4[1];
                bfr[nj + 1][0] = r4[2]; bfr[nj + 1][1] = r4[3];
            }
            #pragma unroll
            for (int mi = 0; mi < MF; mi++)
                #pragma unroll
                for (int nj = 0; nj < NF; nj++)
                    mma16816(acc[mi][nj], afr[mi], bfr[nj]);
        }
    };

    const int T = p.K >> 6;
    loadtile(0, 0);
    for (int t = 0; t < T; t++) {
        const int buf = t & 1;
        if (t + 1 < T) { loadtile(t + 1, buf ^ 1); cp_wait<1>(); }
        else           { cp_wait<0>(); }
        __syncthreads();
        compute(buf);
        __syncthreads();
    }

    // ---------------- epilogue ----------------
    const long long offC = (long long)(z >> 4) * p.sCb + (long long)(z & 15) * p.sCh;
    const int qr = lane >> 2;            // quad row 0..7
    const int qc = (lane & 3) * 2;       // col pair

    if (EPI == 4) {
        #pragma unroll
        for (int mi = 0; mi < MF; mi++) {
            int r0 = m0 + wm + mi * 16 + qr;
            #pragma unroll
            for (int nj = 0; nj < NF; nj++) {
                int col = n0 + wn + nj * 8 + qc;
                const float* R0 = p.resid + (long long)r0 * p.ldc + col;
                const float* R1 = p.resid + (long long)(r0 + 8) * p.ldc + col;
                float2 v0 = make_float2(acc[mi][nj][0] + R0[0], acc[mi][nj][1] + R0[1]);
                float2 v1 = make_float2(acc[mi][nj][2] + R1[0], acc[mi][nj][3] + R1[1]);
                *(float2*)((float*)p.C + offC + (long long)r0 * p.ldc + col) = v0;
                *(float2*)((float*)p.C + offC + (long long)(r0 + 8) * p.ldc + col) = v1;
            }
        }
    } else if (EPI == 2) {
        #pragma unroll
        for (int mi = 0; mi < MF; mi++) {
            int r0 = m0 + wm + mi * 16 + qr;
            float rs0 = 0.f, rs1 = 0.f;
            #pragma unroll
            for (int nj = 0; nj < NF; nj++) {
                int col = n0 + wn + nj * 8 + qc;
                float e0 = __expf(acc[mi][nj][0]);
                float e1 = __expf(acc[mi][nj][1]);
                float e2 = __expf(acc[mi][nj][2]);
                float e3 = __expf(acc[mi][nj][3]);
                rs0 += e0 + e1; rs1 += e2 + e3;
                *(__half2*)((__half*)p.C + offC + (long long)r0 * p.ldc + col) =
                    __floats2half2_rn(e0, e1);
                *(__half2*)((__half*)p.C + offC + (long long)(r0 + 8) * p.ldc + col) =
                    __floats2half2_rn(e2, e3);
            }
            // reduce across the quad (lanes sharing the same rows)
            rs0 += __shfl_xor_sync(0xFFFFFFFFu, rs0, 1);
            rs0 += __shfl_xor_sync(0xFFFFFFFFu, rs0, 2);
            rs1 += __shfl_xor_sync(0xFFFFFFFFu, rs1, 1);
            rs1 += __shfl_xor_sync(0xFFFFFFFFu, rs1, 2);
            if ((lane & 3) == 0) {
                atomicAdd(&p.aux[(long long)z * SS + r0], rs0);
                atomicAdd(&p.aux[(long long)z * SS + r0 + 8], rs1);
            }
        }
    } else {  // EPI 0 or 3
        #pragma unroll
        for (int mi = 0; mi < MF; mi++) {
            int r0 = m0 + wm + mi * 16 + qr;
            float s0 = p.scale, s1 = p.scale;
            if (EPI == 3) {
                s0 = 1.f / p.aux[(long long)z * SS + r0];
                s1 = 1.f / p.aux[(long long)z * SS + r0 + 8];
            }
            #pragma unroll
            for (int nj = 0; nj < NF; nj++) {
                int col = n0 + wn + nj * 8 + qc;
                *(__half2*)((__half*)p.C + offC + (long long)r0 * p.ldc + col) =
                    __floats2half2_rn(acc[mi][nj][0] * s0, acc[mi][nj][1] * s0);
                *(__half2*)((__half*)p.C + offC + (long long)(r0 + 8) * p.ldc + col) =
                    __floats2half2_rn(acc[mi][nj][2] * s1, acc[mi][nj][3] * s1);
            }
        }
    }
}

// ---------------------------------------------------------------------------
// Helper kernels
// ---------------------------------------------------------------------------
__global__ __launch_bounds__(256)
void f2h_kernel(const float* __restrict__ in, __half* __restrict__ out) {
    int idx = blockIdx.x * 256 + threadIdx.x;  // one float4
    float4 v = ((const float4*)in)[idx];
    ((__half2*)out)[2 * idx]     = __floats2half2_rn(v.x, v.y);
    ((__half2*)out)[2 * idx + 1] = __floats2half2_rn(v.z, v.w);
}

__global__ __launch_bounds__(256)
void zero_kernel(float* p) { p[blockIdx.x * 256 + threadIdx.x] = 0.f; }

// in [K][N] fp32 row-major -> out [N][K] fp16
__global__ void transposeW(const float* __restrict__ in, __half* __restrict__ out,
                           int K, int N) {
    __shared__ float t[32][33];
    int k0 = blockIdx.y * 32, n0 = blockIdx.x * 32;
    int tx = threadIdx.x, ty = threadIdx.y;
    #pragma unroll
    for (int i = 0; i < 32; i += 8)
        t[ty + i][tx] = in[(long long)(k0 + ty + i) * N + n0 + tx];
    __syncthreads();
    #pragma unroll
    for (int i = 0; i < 32; i += 8)
        out[(long long)(n0 + ty + i) * K + k0 + tx] = __float2half(t[tx][ty + i]);
}

// vh16 [B*S][D] -> vhT16 [z][d][s]
__global__ void transposeV(const __half* __restrict__ vh, __half* __restrict__ vhT) {
    __shared__ __half t[32][33];
    int z = blockIdx.z, b = z >> 4, h = z & 15;
    int s0 = blockIdx.x * 32, d0 = blockIdx.y * 32;
    int tx = threadIdx.x, ty = threadIdx.y;
    #pragma unroll
    for (int i = 0; i < 32; i += 8)
        t[ty + i][tx] = vh[(long long)(b * SS + s0 + ty + i) * DD + h * DKK + d0 + tx];
    __syncthreads();
    #pragma unroll
    for (int i = 0; i < 32; i += 8)
        vhT[((long long)z * DKK + d0 + ty + i) * SS + s0 + tx] = t[tx][ty + i];
}

// attn fp32 output = exp16 * (1/rowsum)
__global__ __launch_bounds__(256)
void attn_norm(const __half* __restrict__ a16, const float* __restrict__ rowsum,
               float* __restrict__ out) {
    long long row = blockIdx.x;
    float inv = 1.f / rowsum[row];
    const __half2* p = (const __half2*)(a16 + row * SS);
    float2* o = (float2*)(out + row * SS);
    #pragma unroll
    for (int i = threadIdx.x; i < SS / 2; i += 256) {
        float2 f = __half22float2(p[i]);
        o[i] = make_float2(f.x * inv, f.y * inv);
    }
}

// LayerNorm over D=1024, eps=1e-6
__global__ __launch_bounds__(256)
void ln_kernel(const float* __restrict__ x, const float* __restrict__ gamma,
               const float* __restrict__ beta, float* __restrict__ out) {
    __shared__ float reds[8], redq[8];
    const float* p = x + (size_t)blockIdx.x * DD;
    const int tid = threadIdx.x;
    float v[4];
    float s = 0.f, sq = 0.f;
    #pragma unroll
    for (int i = 0; i < 4; i++) {
        v[i] = p[tid + 256 * i];
        s += v[i];
        sq = fmaf(v[i], v[i], sq);
    }
    #pragma unroll
    for (int o = 16; o > 0; o >>= 1) {
        s  += __shfl_xor_sync(0xFFFFFFFFu, s,  o);
        sq += __shfl_xor_sync(0xFFFFFFFFu, sq, o);
    }
    if ((tid & 31) == 0) { reds[tid >> 5] = s; redq[tid >> 5] = sq; }
    __syncthreads();
    s = 0.f; sq = 0.f;
    #pragma unroll
    for (int w = 0; w < 8; w++) { s += reds[w]; sq += redq[w]; }
    const float mean = s * (1.0f / DD);
    const float var  = sq * (1.0f / DD) - mean * mean;
    const float inv  = rsqrtf(var + 1e-6f);
    float* o = out + (size_t)blockIdx.x * DD;
    #pragma unroll
    for (int i = 0; i < 4; i++) {
        int c = tid + 256 * i;
        o[c] = (v[i] - mean) * inv * gamma[c] + beta[c];
    }
}

// ---------------------------------------------------------------------------
extern "C" void kernel_launch(void* const* d_in, const int* in_sizes, int n_in,
                              void* d_out, int out_size)
{
    const float* q      = (const float*)d_in[0];
    const float* k      = (const float*)d_in[1];
    const float* v      = (const float*)d_in[2];
    const float* w_qs_u = (const float*)d_in[3];
    const float* w_qs_v = (const float*)d_in[4];
    const float* w_ks_u = (const float*)d_in[5];
    const float* w_ks_v = (const float*)d_in[6];
    const float* w_vs_u = (const float*)d_in[7];
    const float* w_vs_v = (const float*)d_in[8];
    const float* fc_u   = (const float*)d_in[9];
    const float* fc_v   = (const float*)d_in[10];
    const float* gamma  = (const float*)d_in[11];
    const float* beta   = (const float*)d_in[12];

    __half *q16, *k16, *v16, *tmp16, *qh16, *kh16, *vh16, *vhT16, *ctx16, *attn16;
    __half *wqsuT, *wqsvT, *wksuT, *wksvT, *wvsuT, *wvsvT, *fcuT, *fcvT;
    float *rowsum, *pre;
    cudaGetSymbolAddress((void**)&q16,   g_q16);
    cudaGetSymbolAddress((void**)&k16,   g_k16);
    cudaGetSymbolAddress((void**)&v16,   g_v16);
    cudaGetSymbolAddress((void**)&tmp16, g_tmp16);
    cudaGetSymbolAddress((void**)&qh16,  g_qh16);
    cudaGetSymbolAddress((void**)&kh16,  g_kh16);
    cudaGetSymbolAddress((void**)&vh16,  g_vh16);
    cudaGetSymbolAddress((void**)&vhT16, g_vhT16);
    cudaGetSymbolAddress((void**)&ctx16, g_ctx16);
    cudaGetSymbolAddress((void**)&attn16,g_attn16);
    cudaGetSymbolAddress((void**)&rowsum,g_rowsum);
    cudaGetSymbolAddress((void**)&pre,   g_pre);
    cudaGetSymbolAddress((void**)&wqsuT, g_wqsuT);
    cudaGetSymbolAddress((void**)&wqsvT, g_wqsvT);
    cudaGetSymbolAddress((void**)&wksuT, g_wksuT);
    cudaGetSymbolAddress((void**)&wksvT, g_wksvT);
    cudaGetSymbolAddress((void**)&wvsuT, g_wvsuT);
    cudaGetSymbolAddress((void**)&wvsvT, g_wvsvT);
    cudaGetSymbolAddress((void**)&fcuT,  g_fcuT);
    cudaGetSymbolAddress((void**)&fcvT,  g_fcvT);

    float* outp = nullptr;
    float* attn = nullptr;
    const size_t osz = (size_t)out_size;
    if (osz >= OUT_ELEMS + ATTN_ELEMS) { outp = (float*)d_out; attn = (float*)d_out + OUT_ELEMS; }
    else if (osz == ATTN_ELEMS)        { attn = (float*)d_out; }
    else                               { outp = (float*)d_out; }

    const int SMEM128 = 2 * (128 * 128 + 128 * 128);  // 65536
    const int SMEM64  = 2 * (128 * 128 + 64 * 128);   // 49152
    cudaFuncSetAttribute(hgemm_mma<128, 0>, cudaFuncAttributeMaxDynamicSharedMemorySize, SMEM128);
    cudaFuncSetAttribute(hgemm_mma<128, 2>, cudaFuncAttributeMaxDynamicSharedMemorySize, SMEM128);
    cudaFuncSetAttribute(hgemm_mma<64,  3>, cudaFuncAttributeMaxDynamicSharedMemorySize, SMEM64);
    cudaFuncSetAttribute(hgemm_mma<128, 4>, cudaFuncAttributeMaxDynamicSharedMemorySize, SMEM128);

    // Conversions
    zero_kernel<<<ZBH * SS / 256, 256>>>(rowsum);
    f2h_kernel<<<MROWS * DD / 1024, 256>>>(q, q16);
    f2h_kernel<<<MROWS * DD / 1024, 256>>>(k, k16);
    f2h_kernel<<<MROWS * DD / 1024, 256>>>(v, v16);
    {
        dim3 b(32, 8);
        transposeW<<<dim3(RR / 32, DD / 32), b>>>(w_qs_u, wqsuT, DD, RR);
        transposeW<<<dim3(DD / 32, RR / 32), b>>>(w_qs_v, wqsvT, RR, DD);
        transposeW<<<dim3(RR / 32, DD / 32), b>>>(w_ks_u, wksuT, DD, RR);
        transposeW<<<dim3(DD / 32, RR / 32), b>>>(w_ks_v, wksvT, RR, DD);
        transposeW<<<dim3(RR / 32, DD / 32), b>>>(w_vs_u, wvsuT, DD, RR);
        transposeW<<<dim3(DD / 32, RR / 32), b>>>(w_vs_v, wvsvT, RR, DD);
        transposeW<<<dim3(RR / 32, DD / 32), b>>>(fc_u,   fcuT,  DD, RR);
        transposeW<<<dim3(DD / 32, RR / 32), b>>>(fc_v,   fcvT,  RR, DD);
    }

    GP p{};
    // ---- projections: x @ U -> tmp16 ; tmp16 @ V -> {qh,kh,vh}16
    auto proj = [&](const __half* x16, const __half* uT, const __half* vT,
                    __half* out16, float sc) {
        p = GP{};
        p.A = x16;  p.lda = DD;  p.B = uT;  p.ldb = DD;
        p.C = tmp16; p.ldc = RR; p.K = DD; p.scale = 1.f;
        hgemm_mma<128, 0><<<dim3(RR / 128, MROWS / 128, 1), 256, SMEM128>>>(p);
        p = GP{};
        p.A = tmp16; p.lda = RR; p.B = vT;  p.ldb = RR;
        p.C = out16; p.ldc = DD; p.K = RR;  p.scale = sc;
        hgemm_mma<128, 0><<<dim3(DD / 128, MROWS / 128, 1), 256, SMEM128>>>(p);
    };
    proj(q16, wqsuT, wqsvT, qh16, 0.125f);   // fold 1/sqrt(dk) into qh
    proj(k16, wksuT, wksvT, kh16, 1.f);
    proj(v16, wvsuT, wvsvT, vh16, 1.f);

    transposeV<<<dim3(SS / 32, DKK / 32, ZBH), dim3(32, 8)>>>(vh16, vhT16);

    // ---- scores: exp(qh @ kh^T) per (b,h); unnormalized fp16 + rowsums
    p = GP{};
    p.A = qh16; p.lda = DD; p.sAb = (long long)SS * DD; p.sAh = DKK;
    p.B = kh16; p.ldb = DD; p.sBb = (long long)SS * DD; p.sBh = DKK;
    p.C = attn16; p.ldc = SS;
    p.sCh = (long long)SS * SS; p.sCb = 16LL * SS * SS;
    p.K = DKK; p.aux = rowsum; p.scale = 1.f;
    hgemm_mma<128, 2><<<dim3(SS / 128, SS / 128, ZBH), 256, SMEM128>>>(p);

    if (attn)
        attn_norm<<<ZBH * SS, 256>>>(attn16, rowsum, attn);

    if (outp) {
        // ---- ctx = (exp @ vh) / rowsum  -> ctx16 [B*S][D]
        p = GP{};
        p.A = attn16; p.lda = SS; p.sAh = (long long)SS * SS; p.sAb = 16LL * SS * SS;
        p.B = vhT16;  p.ldb = SS; p.sBh = (long long)DKK * SS; p.sBb = 16LL * DKK * SS;
        p.C = ctx16;  p.ldc = DD; p.sCb = (long long)SS * DD;  p.sCh = DKK;
        p.K = SS; p.aux = rowsum; p.scale = 1.f;
        hgemm_mma<64, 3><<<dim3(1, SS / 128, ZBH), 256, SMEM64>>>(p);

        // ---- FC low-rank + residual, then LN
        p = GP{};
        p.A = ctx16; p.lda = DD; p.B = fcuT; p.ldb = DD;
        p.C = tmp16; p.ldc = RR; p.K = DD; p.scale = 1.f;
        hgemm_mma<128, 0><<<dim3(RR / 128, MROWS / 128, 1), 256, SMEM128>>>(p);

        p = GP{};
        p.A = tmp16; p.lda = RR; p.B = fcvT; p.ldb = RR;
        p.C = pre; p.ldc = DD; p.K = RR; p.resid = q;
        hgemm_mma<128, 4><<<dim3(DD / 128, MROWS / 128, 1), 256, SMEM128>>>(p);

        ln_kernel<<<MROWS, 256>>>(pre, gamma, beta, outp);
    }
}

// round 6
// speedup vs baseline: 5.3888x; 1.2636x over previous
#include <cuda_runtime.h>
#include <cuda_fp16.h>
#include <cstdint>
#include <cstddef>

// Problem constants
#define BB   4
#define SS   2048
#define HH   16
#define DKK  64
#define DD   1024
#define RR   256
#define MROWS (BB*SS)   // 8192
#define ZBH  (BB*HH)    // 64

static const size_t OUT_ELEMS  = (size_t)BB * SS * DD;        // 8388608
static const size_t ATTN_ELEMS = (size_t)BB * HH * SS * SS;   // 268435456

// ---------------------------------------------------------------------------
// Scratch (__device__ globals; allocation-free rule)
// ---------------------------------------------------------------------------
__device__ __align__(128) __half g_q16 [MROWS * DD];
__device__ __align__(128) __half g_k16 [MROWS * DD];
__device__ __align__(128) __half g_v16 [MROWS * DD];
__device__ __align__(128) __half g_tmp16[MROWS * RR];
__device__ __align__(128) __half g_qh16[MROWS * DD];
__device__ __align__(128) __half g_kh16[MROWS * DD];
__device__ __align__(128) __half g_vh16[MROWS * DD];
__device__ __align__(128) __half g_vhT16[(size_t)ZBH * DKK * SS];   // [z][d][s]
__device__ __align__(128) __half g_ctx16[MROWS * DD];
__device__ __align__(128) __half g_attn16[(size_t)ZBH * SS * SS];   // exp(scores)
__device__ __align__(128) float  g_rowsum[(size_t)ZBH * SS];
__device__ __align__(128) float  g_pre [MROWS * DD];
// transposed fp16 weights [N][K]
__device__ __align__(128) __half g_wqsuT[RR * DD];
__device__ __align__(128) __half g_wqsvT[DD * RR];
__device__ __align__(128) __half g_wksuT[RR * DD];
__device__ __align__(128) __half g_wksvT[DD * RR];
__device__ __align__(128) __half g_wvsuT[RR * DD];
__device__ __align__(128) __half g_wvsvT[DD * RR];
__device__ __align__(128) __half g_fcuT [RR * DD];
__device__ __align__(128) __half g_fcvT [DD * RR];

// ---------------------------------------------------------------------------
// PTX helpers (arch-portable: cp.async / ldmatrix / mma.sync only)
// ---------------------------------------------------------------------------
__device__ __forceinline__ uint32_t smem_u32(const void* p) {
    uint32_t a;
    asm("{ .reg .u64 t; cvta.to.shared.u64 t, %1; cvt.u32.u64 %0, t; }" : "=r"(a) : "l"(p));
    return a;
}
__device__ __forceinline__ void cp16(uint32_t d, const void* s) {
    asm volatile("cp.async.cg.shared.global [%0], [%1], 16;" :: "r"(d), "l"(s) : "memory");
}
__device__ __forceinline__ void cp_commit() {
    asm volatile("cp.async.commit_group;" ::: "memory");
}
template<int N> __device__ __forceinline__ void cp_wait() {
    asm volatile("cp.async.wait_group %0;" :: "n"(N) : "memory");
}
__device__ __forceinline__ void ldsm4(uint32_t* r, uint32_t addr) {
    asm volatile("ldmatrix.sync.aligned.m8n8.x4.shared.b16 {%0,%1,%2,%3}, [%4];"
                 : "=r"(r[0]), "=r"(r[1]), "=r"(r[2]), "=r"(r[3]) : "r"(addr));
}
__device__ __forceinline__ void mma16816(float* c, const uint32_t* a, const uint32_t* b) {
    asm volatile("mma.sync.aligned.m16n8k16.row.col.f32.f16.f16.f32 "
                 "{%0,%1,%2,%3}, {%4,%5,%6,%7}, {%8,%9}, {%0,%1,%2,%3};"
                 : "+f"(c[0]), "+f"(c[1]), "+f"(c[2]), "+f"(c[3])
                 : "r"(a[0]), "r"(a[1]), "r"(a[2]), "r"(a[3]), "r"(b[0]), "r"(b[1]));
}
__device__ __forceinline__ uint32_t packh2(float a, float b) {
    __half2 h = __floats2half2_rn(a, b);
    return *(uint32_t*)&h;
}
#define SWZ(o) ((o) ^ (((o) >> 3) & 0x70))

// ---------------------------------------------------------------------------
// HMMA fp16 GEMM: C[M,N] = sum_k A[m,k] * B[n,k]  (A,B K-major fp16)
// Block tile 128 x 128, K-tile 64, 256 threads (8 warps), double-buffered.
// EPI: 0 = fp16 store (* scale), 4 = + resid, fp32 store.
// ---------------------------------------------------------------------------
struct GP {
    const __half* A; const __half* B; void* C;
    const float* resid;
    int lda, ldb, ldc, K;
    float scale;
};

template<int EPI>
__global__ __launch_bounds__(256)
void hgemm_mma(GP p)
{
    constexpr int WM = 64, WN = 32;          // 2x4 warps
    constexpr int MF = 4, NF = 4;
    constexpr int ABYTES = 128 * 128;
    constexpr int BBYTES = 128 * 128;
    constexpr int BUF = ABYTES + BBYTES;

    extern __shared__ char smem[];
    const uint32_t sb = smem_u32(smem);
    const int tid = threadIdx.x, lane = tid & 31, wid = tid >> 5;
    const int wm = (wid >> 2) * WM;
    const int wn = (wid & 3) * WN;

    const int m0 = blockIdx.y * 128;
    const int n0 = blockIdx.x * 128;

    float acc[MF][NF][4];
    #pragma unroll
    for (int i = 0; i < MF; i++)
        #pragma unroll
        for (int j = 0; j < NF; j++)
            #pragma unroll
            for (int e = 0; e < 4; e++) acc[i][j][e] = 0.f;

    auto loadtile = [&](int t, int buf) {
        const uint32_t base = sb + buf * BUF;
        const __half* Ag = p.A + (long long)m0 * p.lda + t * 64;
        #pragma unroll
        for (int i = 0; i < 4; i++) {
            int idx = tid + 256 * i;
            int r = idx >> 3, c = idx & 7;
            cp16(base + SWZ(r * 128 + c * 16), Ag + (long long)r * p.lda + c * 8);
        }
        const __half* Bg = p.B + (long long)n0 * p.ldb + t * 64;
        #pragma unroll
        for (int i = 0; i < 4; i++) {
            int idx = tid + 256 * i;
            int r = idx >> 3, c = idx & 7;
            cp16(base + ABYTES + SWZ(r * 128 + c * 16), Bg + (long long)r * p.ldb + c * 8);
        }
        cp_commit();
    };

    auto compute = [&](int buf) {
        const uint32_t sa = sb + buf * BUF;
        const uint32_t sB = sa + ABYTES;
        #pragma unroll
        for (int kk = 0; kk < 4; kk++) {
            uint32_t afr[MF][4];
            #pragma unroll
            for (int mi = 0; mi < MF; mi++) {
                int row = wm + mi * 16 + (lane & 15);
                ldsm4(afr[mi], sa + SWZ(row * 128 + kk * 32 + (lane >> 4) * 16));
            }
            uint32_t bfr[NF][2];
            #pragma unroll
            for (int nj = 0; nj < NF; nj += 2) {
                int rowb = wn + nj * 8 + (lane & 7) + ((lane >> 4) & 1) * 8;
                uint32_t r4[4];
                ldsm4(r4, sB + SWZ(rowb * 128 + kk * 32 + ((lane >> 3) & 1) * 16));
                bfr[nj][0] = r4[0]; bfr[nj][1] = r4[1];
                bfr[nj + 1][0] = r4[2]; bfr[nj + 1][1] = r4[3];
            }
            #pragma unroll
            for (int mi = 0; mi < MF; mi++)
                #pragma unroll
                for (int nj = 0; nj < NF; nj++)
                    mma16816(acc[mi][nj], afr[mi], bfr[nj]);
        }
    };

    const int T = p.K >> 6;
    loadtile(0, 0);
    for (int t = 0; t < T; t++) {
        const int buf = t & 1;
        if (t + 1 < T) { loadtile(t + 1, buf ^ 1); cp_wait<1>(); }
        else           { cp_wait<0>(); }
        __syncthreads();
        compute(buf);
        __syncthreads();
    }

    const int qr = lane >> 2;
    const int qc = (lane & 3) * 2;

    if (EPI == 4) {
        #pragma unroll
        for (int mi = 0; mi < MF; mi++) {
            int r0 = m0 + wm + mi * 16 + qr;
            #pragma unroll
            for (int nj = 0; nj < NF; nj++) {
                int col = n0 + wn + nj * 8 + qc;
                const float* R0 = p.resid + (long long)r0 * p.ldc + col;
                const float* R1 = p.resid + (long long)(r0 + 8) * p.ldc + col;
                float2 v0 = make_float2(acc[mi][nj][0] + R0[0], acc[mi][nj][1] + R0[1]);
                float2 v1 = make_float2(acc[mi][nj][2] + R1[0], acc[mi][nj][3] + R1[1]);
                *(float2*)((float*)p.C + (long long)r0 * p.ldc + col) = v0;
                *(float2*)((float*)p.C + (long long)(r0 + 8) * p.ldc + col) = v1;
            }
        }
    } else {
        #pragma unroll
        for (int mi = 0; mi < MF; mi++) {
            int r0 = m0 + wm + mi * 16 + qr;
            #pragma unroll
            for (int nj = 0; nj < NF; nj++) {
                int col = n0 + wn + nj * 8 + qc;
                *(__half2*)((__half*)p.C + (long long)r0 * p.ldc + col) =
                    __floats2half2_rn(acc[mi][nj][0] * p.scale, acc[mi][nj][1] * p.scale);
                *(__half2*)((__half*)p.C + (long long)(r0 + 8) * p.ldc + col) =
                    __floats2half2_rn(acc[mi][nj][2] * p.scale, acc[mi][nj][3] * p.scale);
            }
        }
    }
}

// ---------------------------------------------------------------------------
// Fused attention: per block = (z, 128-row q tile).
//   S = qh @ kh^T (scale pre-folded), E = exp(S) -> attn16 (unnormalized fp16)
//   rowsum computed in-block (no atomics), O = (E @ V) / rowsum -> ctx16
// 8 warps, each owns 16 q rows. K/V chunks of 128 seq positions, double-buffered.
// ---------------------------------------------------------------------------
__global__ __launch_bounds__(256)
void flash_kernel(const __half* __restrict__ qh, const __half* __restrict__ kh,
                  const __half* __restrict__ vhT, __half* __restrict__ attn16,
                  float* __restrict__ rowsum, __half* __restrict__ ctx16)
{
    constexpr int KB  = 128 * 128;           // K chunk: 128 rows x 128B
    constexpr int VB  = 2 * 64 * 128;        // V chunk: two 64x64 subtiles
    constexpr int BUF = KB + VB;             // 32 KB

    extern __shared__ char smem[];
    const uint32_t sq  = smem_u32(smem);     // Q tile 16 KB
    const uint32_t sk0 = sq + 16384;
    const int tid = threadIdx.x, lane = tid & 31, w = tid >> 5;
    const int z = blockIdx.y, b = z >> 4, h = z & 15;
    const int i0 = blockIdx.x * 128;

    const __half* Qg = qh + (long long)(b * SS + i0) * DD + h * DKK;
    const __half* Kg = kh + (long long)(b * SS) * DD + h * DKK;
    const __half* Vg = vhT + (long long)z * DKK * SS;

    // Q tile once
    #pragma unroll
    for (int i = 0; i < 4; i++) {
        int idx = tid + 256 * i;
        int r = idx >> 3, c = idx & 7;
        cp16(sq + SWZ(r * 128 + c * 16), Qg + (long long)r * DD + c * 8);
    }
    cp_commit();

    auto loadKV = [&](int j, int buf) {
        const uint32_t base = sk0 + buf * BUF;
        const __half* Kc = Kg + (long long)j * 128 * DD;
        #pragma unroll
        for (int i = 0; i < 4; i++) {
            int idx = tid + 256 * i;
            int r = idx >> 3, c = idx & 7;
            cp16(base + SWZ(r * 128 + c * 16), Kc + (long long)r * DD + c * 8);
        }
        #pragma unroll
        for (int s2 = 0; s2 < 2; s2++)
            #pragma unroll
            for (int i = 0; i < 2; i++) {
                int idx = tid + 256 * i;
                int r = idx >> 3, c = idx & 7;   // r in 0..63 (d), c col group
                cp16(base + KB + s2 * 8192 + SWZ(r * 128 + c * 16),
                     Vg + (long long)r * SS + j * 128 + s2 * 64 + c * 8);
            }
        cp_commit();
    };

    float Oacc[8][4];
    #pragma unroll
    for (int i = 0; i < 8; i++)
        #pragma unroll
        for (int e = 0; e < 4; e++) Oacc[i][e] = 0.f;
    float rs0 = 0.f, rs1 = 0.f;

    const int qr = lane >> 2;
    const int qc = (lane & 3) * 2;
    const int rloc = w * 16 + qr;                 // local row (0..127)
    const long long arow0 = ((long long)z * SS + i0 + rloc) * SS + qc;

    loadKV(0, 0);
    for (int j = 0; j < 16; j++) {
        const int buf = j & 1;
        if (j + 1 < 16) { loadKV(j + 1, buf ^ 1); cp_wait<1>(); }
        else            { cp_wait<0>(); }
        __syncthreads();

        const uint32_t sk = sk0 + buf * BUF;
        const uint32_t sv = sk + KB;

        // scores: warp's 16 rows x 128 cols
        float S[16][4];
        #pragma unroll
        for (int nt = 0; nt < 16; nt++)
            #pragma unroll
            for (int e = 0; e < 4; e++) S[nt][e] = 0.f;

        #pragma unroll
        for (int kk = 0; kk < 4; kk++) {
            uint32_t afr[4];
            int row = w * 16 + (lane & 15);
            ldsm4(afr, sq + SWZ(row * 128 + kk * 32 + (lane >> 4) * 16));
            #pragma unroll
            for (int nj = 0; nj < 16; nj += 2) {
                int rowb = nj * 8 + (lane & 7) + ((lane >> 4) & 1) * 8;
                uint32_t r4[4];
                ldsm4(r4, sk + SWZ(rowb * 128 + kk * 32 + ((lane >> 3) & 1) * 16));
                uint32_t b0[2] = { r4[0], r4[1] }, b1[2] = { r4[2], r4[3] };
                mma16816(S[nj], afr, b0);
                mma16816(S[nj + 1], afr, b1);
            }
        }

        // exp, rowsum, store exp16, pack into A-fragments
        uint32_t P0[16], P1[16];
        #pragma unroll
        for (int nt = 0; nt < 16; nt++) {
            float e0 = __expf(S[nt][0]);
            float e1 = __expf(S[nt][1]);
            float e2 = __expf(S[nt][2]);
            float e3 = __expf(S[nt][3]);
            rs0 += e0 + e1; rs1 += e2 + e3;
            P0[nt] = packh2(e0, e1);
            P1[nt] = packh2(e2, e3);
            *(uint32_t*)(attn16 + arow0 + j * 128 + nt * 8)           = P0[nt];
            *(uint32_t*)(attn16 + arow0 + 8LL * SS + j * 128 + nt * 8) = P1[nt];
        }

        // O += P @ V  (K = 128 seq positions of this chunk)
        #pragma unroll
        for (int kc = 0; kc < 8; kc++) {
            uint32_t a[4] = { P0[2 * kc], P1[2 * kc], P0[2 * kc + 1], P1[2 * kc + 1] };
            const uint32_t svb = sv + (kc >> 2) * 8192;
            const int kk2 = kc & 3;
            #pragma unroll
            for (int nj = 0; nj < 8; nj += 2) {
                int rowb = nj * 8 + (lane & 7) + ((lane >> 4) & 1) * 8;
                uint32_t r4[4];
                ldsm4(r4, svb + SWZ(rowb * 128 + kk2 * 32 + ((lane >> 3) & 1) * 16));
                uint32_t b0[2] = { r4[0], r4[1] }, b1[2] = { r4[2], r4[3] };
                mma16816(Oacc[nj], a, b0);
                mma16816(Oacc[nj + 1], a, b1);
            }
        }
        __syncthreads();
    }

    // finalize rowsum (quad reduce: lanes sharing rows)
    rs0 += __shfl_xor_sync(0xFFFFFFFFu, rs0, 1);
    rs0 += __shfl_xor_sync(0xFFFFFFFFu, rs0, 2);
    rs1 += __shfl_xor_sync(0xFFFFFFFFu, rs1, 1);
    rs1 += __shfl_xor_sync(0xFFFFFFFFu, rs1, 2);
    const int r0g = i0 + rloc;
    if ((lane & 3) == 0) {
        rowsum[(long long)z * SS + r0g]     = rs0;
        rowsum[(long long)z * SS + r0g + 8] = rs1;
    }
    const float inv0 = 1.f / rs0, inv1 = 1.f / rs1;

    // store ctx16 [b*SS + row][h*64 + col]
    #pragma unroll
    for (int nj = 0; nj < 8; nj++) {
        int col = h * DKK + nj * 8 + qc;
        *(__half2*)(ctx16 + (long long)(b * SS + r0g) * DD + col) =
            __floats2half2_rn(Oacc[nj][0] * inv0, Oacc[nj][1] * inv0);
        *(__half2*)(ctx16 + (long long)(b * SS + r0g + 8) * DD + col) =
            __floats2half2_rn(Oacc[nj][2] * inv1, Oacc[nj][3] * inv1);
    }
}

// ---------------------------------------------------------------------------
// Helper kernels
// ---------------------------------------------------------------------------
__global__ __launch_bounds__(256)
void f2h_kernel(const float* __restrict__ in, __half* __restrict__ out) {
    int idx = blockIdx.x * 256 + threadIdx.x;  // one float4
    float4 v = ((const float4*)in)[idx];
    ((__half2*)out)[2 * idx]     = __floats2half2_rn(v.x, v.y);
    ((__half2*)out)[2 * idx + 1] = __floats2half2_rn(v.z, v.w);
}

// in [K][N] fp32 row-major -> out [N][K] fp16
__global__ void transposeW(const float* __restrict__ in, __half* __restrict__ out,
                           int K, int N) {
    __shared__ float t[32][33];
    int k0 = blockIdx.y * 32, n0 = blockIdx.x * 32;
    int tx = threadIdx.x, ty = threadIdx.y;
    #pragma unroll
    for (int i = 0; i < 32; i += 8)
        t[ty + i][tx] = in[(long long)(k0 + ty + i) * N + n0 + tx];
    __syncthreads();
    #pragma unroll
    for (int i = 0; i < 32; i += 8)
        out[(long long)(n0 + ty + i) * K + k0 + tx] = __float2half(t[tx][ty + i]);
}

// vh16 [B*S][D] -> vhT16 [z][d][s]
__global__ void transposeV(const __half* __restrict__ vh, __half* __restrict__ vhT) {
    __shared__ __half t[32][33];
    int z = blockIdx.z, b = z >> 4, h = z & 15;
    int s0 = blockIdx.x * 32, d0 = blockIdx.y * 32;
    int tx = threadIdx.x, ty = threadIdx.y;
    #pragma unroll
    for (int i = 0; i < 32; i += 8)
        t[ty + i][tx] = vh[(long long)(b * SS + s0 + ty + i) * DD + h * DKK + d0 + tx];
    __syncthreads();
    #pragma unroll
    for (int i = 0; i < 32; i += 8)
        vhT[((long long)z * DKK + d0 + ty + i) * SS + s0 + tx] = t[tx][ty + i];
}

// attn fp32 output = exp16 * (1/rowsum), vectorized uint4 -> 2x float4
__global__ __launch_bounds__(256)
void attn_norm(const __half* __restrict__ a16, const float* __restrict__ rowsum,
               float* __restrict__ out) {
    long long row = blockIdx.x;
    float inv = 1.f / rowsum[row];
    uint4 v = ((const uint4*)(a16 + row * SS))[threadIdx.x];
    const __half2* hp = (const __half2*)&v;
    float2 f0 = __half22float2(hp[0]);
    float2 f1 = __half22float2(hp[1]);
    float2 f2 = __half22float2(hp[2]);
    float2 f3 = __half22float2(hp[3]);
    float4* o = (float4*)(out + row * SS) + 2 * threadIdx.x;
    o[0] = make_float4(f0.x * inv, f0.y * inv, f1.x * inv, f1.y * inv);
    o[1] = make_float4(f2.x * inv, f2.y * inv, f3.x * inv, f3.y * inv);
}

// LayerNorm over D=1024, eps=1e-6
__global__ __launch_bounds__(256)
void ln_kernel(const float* __restrict__ x, const float* __restrict__ gamma,
               const float* __restrict__ beta, float* __restrict__ out) {
    __shared__ float reds[8], redq[8];
    const float* p = x + (size_t)blockIdx.x * DD;
    const int tid = threadIdx.x;
    float v[4];
    float s = 0.f, sq = 0.f;
    #pragma unroll
    for (int i = 0; i < 4; i++) {
        v[i] = p[tid + 256 * i];
        s += v[i];
        sq = fmaf(v[i], v[i], sq);
    }
    #pragma unroll
    for (int o = 16; o > 0; o >>= 1) {
        s  += __shfl_xor_sync(0xFFFFFFFFu, s,  o);
        sq += __shfl_xor_sync(0xFFFFFFFFu, sq, o);
    }
    if ((tid & 31) == 0) { reds[tid >> 5] = s; redq[tid >> 5] = sq; }
    __syncthreads();
    s = 0.f; sq = 0.f;
    #pragma unroll
    for (int w = 0; w < 8; w++) { s += reds[w]; sq += redq[w]; }
    const float mean = s * (1.0f / DD);
    const float var  = sq * (1.0f / DD) - mean * mean;
    const float inv  = rsqrtf(var + 1e-6f);
    float* o = out + (size_t)blockIdx.x * DD;
    #pragma unroll
    for (int i = 0; i < 4; i++) {
        int c = tid + 256 * i;
        o[c] = (v[i] - mean) * inv * gamma[c] + beta[c];
    }
}

// ---------------------------------------------------------------------------
extern "C" void kernel_launch(void* const* d_in, const int* in_sizes, int n_in,
                              void* d_out, int out_size)
{
    const float* q      = (const float*)d_in[0];
    const float* k      = (const float*)d_in[1];
    const float* v      = (const float*)d_in[2];
    const float* w_qs_u = (const float*)d_in[3];
    const float* w_qs_v = (const float*)d_in[4];
    const float* w_ks_u = (const float*)d_in[5];
    const float* w_ks_v = (const float*)d_in[6];
    const float* w_vs_u = (const float*)d_in[7];
    const float* w_vs_v = (const float*)d_in[8];
    const float* fc_u   = (const float*)d_in[9];
    const float* fc_v   = (const float*)d_in[10];
    const float* gamma  = (const float*)d_in[11];
    const float* beta   = (const float*)d_in[12];

    __half *q16, *k16, *v16, *tmp16, *qh16, *kh16, *vh16, *vhT16, *ctx16, *attn16;
    __half *wqsuT, *wqsvT, *wksuT, *wksvT, *wvsuT, *wvsvT, *fcuT, *fcvT;
    float *rowsum, *pre;
    cudaGetSymbolAddress((void**)&q16,   g_q16);
    cudaGetSymbolAddress((void**)&k16,   g_k16);
    cudaGetSymbolAddress((void**)&v16,   g_v16);
    cudaGetSymbolAddress((void**)&tmp16, g_tmp16);
    cudaGetSymbolAddress((void**)&qh16,  g_qh16);
    cudaGetSymbolAddress((void**)&kh16,  g_kh16);
    cudaGetSymbolAddress((void**)&vh16,  g_vh16);
    cudaGetSymbolAddress((void**)&vhT16, g_vhT16);
    cudaGetSymbolAddress((void**)&ctx16, g_ctx16);
    cudaGetSymbolAddress((void**)&attn16,g_attn16);
    cudaGetSymbolAddress((void**)&rowsum,g_rowsum);
    cudaGetSymbolAddress((void**)&pre,   g_pre);
    cudaGetSymbolAddress((void**)&wqsuT, g_wqsuT);
    cudaGetSymbolAddress((void**)&wqsvT, g_wqsvT);
    cudaGetSymbolAddress((void**)&wksuT, g_wksuT);
    cudaGetSymbolAddress((void**)&wksvT, g_wksvT);
    cudaGetSymbolAddress((void**)&wvsuT, g_wvsuT);
    cudaGetSymbolAddress((void**)&wvsvT, g_wvsvT);
    cudaGetSymbolAddress((void**)&fcuT,  g_fcuT);
    cudaGetSymbolAddress((void**)&fcvT,  g_fcvT);

    float* outp = nullptr;
    float* attn = nullptr;
    const size_t osz = (size_t)out_size;
    if (osz >= OUT_ELEMS + ATTN_ELEMS) { outp = (float*)d_out; attn = (float*)d_out + OUT_ELEMS; }
    else if (osz == ATTN_ELEMS)        { attn = (float*)d_out; }
    else                               { outp = (float*)d_out; }

    const int SMEM_G = 2 * (128 * 128 + 128 * 128);       // 65536
    const int SMEM_F = 16384 + 2 * (128 * 128 + 2 * 64 * 128);  // 81920
    cudaFuncSetAttribute(hgemm_mma<0>, cudaFuncAttributeMaxDynamicSharedMemorySize, SMEM_G);
    cudaFuncSetAttribute(hgemm_mma<4>, cudaFuncAttributeMaxDynamicSharedMemorySize, SMEM_G);
    cudaFuncSetAttribute(flash_kernel, cudaFuncAttributeMaxDynamicSharedMemorySize, SMEM_F);

    // Conversions
    f2h_kernel<<<MROWS * DD / 1024, 256>>>(q, q16);
    f2h_kernel<<<MROWS * DD / 1024, 256>>>(k, k16);
    f2h_kernel<<<MROWS * DD / 1024, 256>>>(v, v16);
    {
        dim3 bb(32, 8);
        transposeW<<<dim3(RR / 32, DD / 32), bb>>>(w_qs_u, wqsuT, DD, RR);
        transposeW<<<dim3(DD / 32, RR / 32), bb>>>(w_qs_v, wqsvT, RR, DD);
        transposeW<<<dim3(RR / 32, DD / 32), bb>>>(w_ks_u, wksuT, DD, RR);
        transposeW<<<dim3(DD / 32, RR / 32), bb>>>(w_ks_v, wksvT, RR, DD);
        transposeW<<<dim3(RR / 32, DD / 32), bb>>>(w_vs_u, wvsuT, DD, RR);
        transposeW<<<dim3(DD / 32, RR / 32), bb>>>(w_vs_v, wvsvT, RR, DD);
        transposeW<<<dim3(RR / 32, DD / 32), bb>>>(fc_u,   fcuT,  DD, RR);
        transposeW<<<dim3(DD / 32, RR / 32), bb>>>(fc_v,   fcvT,  RR, DD);
    }

    GP p{};
    // ---- projections: x @ U -> tmp16 ; tmp16 @ V -> {qh,kh,vh}16
    auto proj = [&](const __half* x16, const __half* uT, const __half* vT,
                    __half* out16, float sc) {
        p = GP{};
        p.A = x16;  p.lda = DD;  p.B = uT;  p.ldb = DD;
        p.C = tmp16; p.ldc = RR; p.K = DD; p.scale = 1.f;
        hgemm_mma<0><<<dim3(RR / 128, MROWS / 128), 256, SMEM_G>>>(p);
        p = GP{};
        p.A = tmp16; p.lda = RR; p.B = vT;  p.ldb = RR;
        p.C = out16; p.ldc = DD; p.K = RR;  p.scale = sc;
        hgemm_mma<0><<<dim3(DD / 128, MROWS / 128), 256, SMEM_G>>>(p);
    };
    proj(q16, wqsuT, wqsvT, qh16, 0.125f);   // fold 1/sqrt(dk) into qh
    proj(k16, wksuT, wksvT, kh16, 1.f);
    proj(v16, wvsuT, wvsvT, vh16, 1.f);

    transposeV<<<dim3(SS / 32, DKK / 32, ZBH), dim3(32, 8)>>>(vh16, vhT16);

    // ---- fused attention: exp16 -> attn16, rowsums, ctx16
    flash_kernel<<<dim3(SS / 128, ZBH), 256, SMEM_F>>>(qh16, kh16, vhT16,
                                                       attn16, rowsum, ctx16);

    if (outp) {
        // ---- FC low-rank + residual, then LN
        p = GP{};
        p.A = ctx16; p.lda = DD; p.B = fcuT; p.ldb = DD;
        p.C = tmp16; p.ldc = RR; p.K = DD; p.scale = 1.f;
        hgemm_mma<0><<<dim3(RR / 128, MROWS / 128), 256, SMEM_G>>>(p);

        p = GP{};
        p.A = tmp16; p.lda = RR; p.B = fcvT; p.ldb = RR;
        p.C = pre; p.ldc = DD; p.K = RR; p.resid = q;
        hgemm_mma<4><<<dim3(DD / 128, MROWS / 128), 256, SMEM_G>>>(p);

        ln_kernel<<<MROWS, 256>>>(pre, gamma, beta, outp);
    }

    if (attn)
        attn_norm<<<ZBH * SS, 256>>>(attn16, rowsum, attn);
}